// round 14
// baseline (speedup 1.0000x reference)
#include <cuda_runtime.h>
#include <cuda_bf16.h>
#include <cstdint>

// Problem constants
#define NN   64
#define LL   1024
#define DD   512
#define LI_  1022
#define SS   127
#define OUTC 300
#define EPSF 1e-5f
#define MR   8128          // NN*SS

#define KT2  1024          // g_B row: [Bh(512) | Bl(512)]
#define NCHK 8             // 8 K-chunks of 64

// Global scratch (allocation-free rule)
__device__ __align__(128) __nv_bfloat16 g_B[(size_t)320 * KT2];

__device__ __forceinline__ uint32_t smem_u32(const void* p) {
    return (uint32_t)__cvta_generic_to_shared(p);
}
__device__ __forceinline__ void ldsm_x4(uint32_t addr, uint32_t& r0, uint32_t& r1,
                                        uint32_t& r2, uint32_t& r3) {
    asm volatile("ldmatrix.sync.aligned.m8n8.x4.shared.b16 {%0,%1,%2,%3}, [%4];"
                 : "=r"(r0), "=r"(r1), "=r"(r2), "=r"(r3) : "r"(addr));
}
__device__ __forceinline__ void ldsm_x2(uint32_t addr, uint32_t& r0, uint32_t& r1) {
    asm volatile("ldmatrix.sync.aligned.m8n8.x2.shared.b16 {%0,%1}, [%2];"
                 : "=r"(r0), "=r"(r1) : "r"(addr));
}
__device__ __forceinline__ void mma16816(float* c, const uint32_t* a,
                                         uint32_t b0, uint32_t b1) {
    asm volatile("mma.sync.aligned.m16n8k16.row.col.f32.bf16.bf16.f32 "
                 "{%0,%1,%2,%3}, {%4,%5,%6,%7}, {%8,%9}, {%0,%1,%2,%3};"
                 : "+f"(c[0]), "+f"(c[1]), "+f"(c[2]), "+f"(c[3])
                 : "r"(a[0]), "r"(a[1]), "r"(a[2]), "r"(a[3]), "r"(b0), "r"(b1));
}
__device__ __forceinline__ void cp_async16(uint32_t dst, const void* src) {
    asm volatile("cp.async.cg.shared.global [%0], [%1], 16;" :: "r"(dst), "l"(src));
}
__device__ __forceinline__ void cp_async_arrive_noinc(uint32_t mbar) {
    asm volatile("cp.async.mbarrier.arrive.noinc.shared.b64 [%0];"
                 :: "r"(mbar) : "memory");
}
__device__ __forceinline__ void mbar_init(uint32_t mbar, uint32_t cnt) {
    asm volatile("mbarrier.init.shared.b64 [%0], %1;" :: "r"(mbar), "r"(cnt) : "memory");
}
__device__ __forceinline__ void mbar_arrive(uint32_t mbar) {
    asm volatile("mbarrier.arrive.release.cta.shared::cta.b64 _, [%0];"
                 :: "r"(mbar) : "memory");
}
__device__ __forceinline__ void mbar_wait(uint32_t mbar, uint32_t parity) {
    uint32_t done;
    asm volatile("{\n\t.reg .pred p;\n\t"
                 "mbarrier.try_wait.parity.acquire.cta.shared::cta.b64 p, [%1], %2;\n\t"
                 "selp.b32 %0, 1, 0, p;\n\t}"
                 : "=r"(done) : "r"(mbar), "r"(parity) : "memory");
    if (!done) {
        asm volatile("{\n\t.reg .pred P1;\n\t"
                     "WL_%=:\n\t"
                     "mbarrier.try_wait.parity.acquire.cta.shared::cta.b64 P1, [%0], %1, 0x989680;\n\t"
                     "@P1 bra.uni WD_%=;\n\t"
                     "bra.uni WL_%=;\n\t"
                     "WD_%=:\n\t}"
                     :: "r"(mbar), "r"(parity) : "memory");
    }
}
__device__ __forceinline__ uint32_t pack_bf2(float a, float b) {
    __nv_bfloat162 p = __float22bfloat162_rn(make_float2(a, b));
    return *(uint32_t*)&p;
}

// ---------------------------------------------------------------------------
// Kernel 1 (light prep): W split -> g_B [Bh|Bl] + use = t1[:,0,:] copy.
// grid = 384: b<320 W rows; b>=320 use rows. 128 threads.
// ---------------------------------------------------------------------------
__global__ void prep_kernel(const float* __restrict__ t1,
                            const float* __restrict__ W,
                            float* __restrict__ out_use)
{
    int b  = blockIdx.x;
    int d4 = threadIdx.x;

    if (b >= 320) {
        int n = b - 320;
        ((float4*)(out_use + (size_t)n * DD))[d4] =
            ((const float4*)(t1 + (size_t)n * LL * DD))[d4];
        return;
    }
    int c  = b;
    int k4 = d4 * 4;
    __nv_bfloat16* Brow = g_B + (size_t)c * KT2;
    if (c >= OUTC) {
        uint2 z = make_uint2(0u, 0u);
        *(uint2*)(Brow + k4)       = z;
        *(uint2*)(Brow + 512 + k4) = z;
        return;
    }
    float4 wv = *(const float4*)(W + (size_t)c * DD + k4);
    __nv_bfloat16 h0 = __float2bfloat16(wv.x), h1 = __float2bfloat16(wv.y);
    __nv_bfloat16 h2 = __float2bfloat16(wv.z), h3 = __float2bfloat16(wv.w);
    __nv_bfloat16 l0 = __float2bfloat16(wv.x - __bfloat162float(h0));
    __nv_bfloat16 l1 = __float2bfloat16(wv.y - __bfloat162float(h1));
    __nv_bfloat16 l2 = __float2bfloat16(wv.z - __bfloat162float(h2));
    __nv_bfloat16 l3 = __float2bfloat16(wv.w - __bfloat162float(h3));
    __nv_bfloat16 hbuf[4] = {h0, h1, h2, h3};
    __nv_bfloat16 lbuf[4] = {l0, l1, l2, l3};
    *(uint2*)(Brow + k4)       = *(uint2*)hbuf;
    *(uint2*)(Brow + 512 + k4) = *(uint2*)lbuf;
}

// ---------------------------------------------------------------------------
// Kernel 2: fully fused, 3-role warp-specialized.
// 640 threads: warps 0-15 consumers (2 row x 8 col groups, 32x40/warp),
//              warps 16-17 B-producers (cp.async, 4-slot ring, 16 fills),
//              warps 18-19 A-producers (t1 LDG -> span means -> split-bf16
//                                       -> STS into 2-chunk A ring).
// Chunk-major: chunk c -> stages (Ah*Bh, Al*Bh, Ah*Bl).
// ---------------------------------------------------------------------------
#define B_SLOT 40960
#define A_OFF  (4 * B_SLOT)                  // 163840
#define DYN_SMEM (A_OFF + 4 * 8192)          // 196608
#define NPROD 64

__global__ __launch_bounds__(640, 1)
void fused_kernel(const float* __restrict__ t1,
                  const int* __restrict__ ws32,
                  const float* __restrict__ blin,
                  const float* __restrict__ gamma,
                  const float* __restrict__ beta,
                  float* __restrict__ out)
{
    extern __shared__ __align__(1024) char dyns[];
    __shared__ __align__(8) uint64_t mbFullB[4], mbEmptyB[4], mbFullA[2], mbEmptyA[2];
    __shared__ float sBias[320], sGamma[320], sBeta[320];
    __shared__ float sRed[8][2][64];
    __shared__ float sMu[64], sInv[64];

    int t    = threadIdx.x;
    int w    = t >> 5;
    int lane = t & 31;
    int ctaRow = blockIdx.x * 64;

    uint32_t dsm    = smem_u32(dyns);
    uint32_t fullB  = smem_u32(&mbFullB[0]);
    uint32_t emptyB = smem_u32(&mbEmptyB[0]);
    uint32_t fullA  = smem_u32(&mbFullA[0]);
    uint32_t emptyA = smem_u32(&mbEmptyA[0]);

    for (int i = t; i < 320; i += 640) {
        sBias[i]  = (i < OUTC) ? blin[i]  : 0.f;
        sGamma[i] = (i < OUTC) ? gamma[i] : 0.f;
        sBeta[i]  = (i < OUTC) ? beta[i]  : 0.f;
    }
    if (t == 0) {
#pragma unroll
        for (int i = 0; i < 4; i++) {
            mbar_init(fullB + 8 * i, NPROD);
            mbar_init(emptyB + 8 * i, 16);
        }
#pragma unroll
        for (int i = 0; i < 2; i++) {
            mbar_init(fullA + 8 * i, NPROD);
            mbar_init(emptyA + 8 * i, 16);
        }
    }
    __syncthreads();

    if (w >= 18) {
        // =================== A-PRODUCER (warps 18,19) ===================
        int pt = t - 576;                 // 0..63
        int slot8 = pt & 7;               // 16B slot within 64-float chunk row
        // 8 spans per thread: sp_i = (pt>>3) + 8*i
        const float* rowPtrs[8];
        int   cnts[8];
        float invCnts[8];
        uint32_t stsBase = (uint32_t)((pt >> 3) * 128) +
                           ((uint32_t)(slot8 * 16) ^ ((uint32_t)(pt >> 3) << 4));
        bool is64 = (ws32[1] == 0 && ws32[3] == 0);
#pragma unroll
        for (int i = 0; i < 8; i++) {
            int gs = ctaRow + (pt >> 3) + 8 * i;
            int n = gs / SS;
            long long start, end;
            if (is64) {
                const long long* ws64 = (const long long*)ws32;
                start = ws64[(size_t)gs * 2];
                end   = ws64[(size_t)gs * 2 + 1];
            } else {
                start = ws32[(size_t)gs * 2];
                end   = ws32[(size_t)gs * 2 + 1];
            }
            if (start > (long long)(LI_ - 1)) start = LI_ - 1;
            if (end   > (long long)LI_)       end   = LI_;
            cnts[i]    = (int)(end - start);
            invCnts[i] = 1.0f / (float)cnts[i];
            rowPtrs[i] = t1 + ((size_t)n * LL + 1 + (size_t)start) * DD + slot8 * 8;
        }

#pragma unroll 1
        for (int c = 0; c < NCHK; ++c) {
            if (c >= 2) mbar_wait(emptyA + 8 * (c & 1), (uint32_t)(((c >> 1) - 1) & 1));
            uint32_t ahOff = A_OFF + (uint32_t)(c & 1) * 16384;
#pragma unroll
            for (int i = 0; i < 8; i++) {
                const float* p = rowPtrs[i] + c * 64;
                float4 s0 = make_float4(0.f, 0.f, 0.f, 0.f);
                float4 s1 = make_float4(0.f, 0.f, 0.f, 0.f);
                if (cnts[i] == 8) {
                    float4 va[8], vb[8];
#pragma unroll
                    for (int r = 0; r < 8; r++) {
                        va[r] = *(const float4*)(p + (size_t)r * DD);
                        vb[r] = *(const float4*)(p + (size_t)r * DD + 4);
                    }
#pragma unroll
                    for (int r = 0; r < 8; r++) {
                        s0.x += va[r].x; s0.y += va[r].y; s0.z += va[r].z; s0.w += va[r].w;
                        s1.x += vb[r].x; s1.y += vb[r].y; s1.z += vb[r].z; s1.w += vb[r].w;
                    }
                } else {
                    for (int r = 0; r < cnts[i]; r++) {
                        float4 a = *(const float4*)(p + (size_t)r * DD);
                        float4 b = *(const float4*)(p + (size_t)r * DD + 4);
                        s0.x += a.x; s0.y += a.y; s0.z += a.z; s0.w += a.w;
                        s1.x += b.x; s1.y += b.y; s1.z += b.z; s1.w += b.w;
                    }
                }
                float ic = invCnts[i];
                s0.x *= ic; s0.y *= ic; s0.z *= ic; s0.w *= ic;
                s1.x *= ic; s1.y *= ic; s1.z *= ic; s1.w *= ic;

                float h[8];
                h[0] = __bfloat162float(__float2bfloat16(s0.x));
                h[1] = __bfloat162float(__float2bfloat16(s0.y));
                h[2] = __bfloat162float(__float2bfloat16(s0.z));
                h[3] = __bfloat162float(__float2bfloat16(s0.w));
                h[4] = __bfloat162float(__float2bfloat16(s1.x));
                h[5] = __bfloat162float(__float2bfloat16(s1.y));
                h[6] = __bfloat162float(__float2bfloat16(s1.z));
                h[7] = __bfloat162float(__float2bfloat16(s1.w));
                uint4 hi, lo;
                hi.x = pack_bf2(h[0], h[1]); hi.y = pack_bf2(h[2], h[3]);
                hi.z = pack_bf2(h[4], h[5]); hi.w = pack_bf2(h[6], h[7]);
                lo.x = pack_bf2(s0.x - h[0], s0.y - h[1]);
                lo.y = pack_bf2(s0.z - h[2], s0.w - h[3]);
                lo.z = pack_bf2(s1.x - h[4], s1.y - h[5]);
                lo.w = pack_bf2(s1.z - h[6], s1.w - h[7]);

                uint32_t so = stsBase + 1024u * i;
                *(uint4*)(dyns + ahOff + so)        = hi;   // Ah
                *(uint4*)(dyns + ahOff + 8192 + so) = lo;   // Al
            }
            mbar_arrive(fullA + 8 * (c & 1));   // release; count=64
        }
    } else if (w >= 16) {
        // =================== B-PRODUCER (warps 16,17) ===================
        int pt = t - 512;                       // 0..63
        const uint4* gB = (const uint4*)g_B;    // row stride 128 uint4
#pragma unroll 1
        for (int f = 0; f < 16; ++f) {
            int slot = f & 3;
            if (f >= 4) mbar_wait(emptyB + 8 * slot, (uint32_t)(((f >> 2) - 1) & 1));
            int c = f >> 1, part = f & 1;
            int bK4 = part * 64 + c * 8;
            uint32_t b_s = dsm + (uint32_t)slot * B_SLOT;
#pragma unroll
            for (int i = 0; i < 40; i++) {
                int j = pt + NPROD * i;
                int row = j >> 3, q = j & 7;
                uint32_t off = (uint32_t)(row * 128 + q * 16);
                cp_async16(b_s + (off ^ ((uint32_t)(row & 7) << 4)),
                           gB + (size_t)row * 128 + bK4 + q);
            }
            cp_async_arrive_noinc(fullB + 8 * slot);
        }
    } else {
        // =================== CONSUMERS (warps 0-15) ===================
        int wr = w & 1;        // rows 32*wr .. 32*wr+31
        int wc = w >> 1;       // cols 40*wc .. 40*wc+39

        float acc[2][5][4];
#pragma unroll
        for (int mi = 0; mi < 2; mi++)
#pragma unroll
            for (int ni = 0; ni < 5; ni++)
#pragma unroll
                for (int r = 0; r < 4; r++) acc[mi][ni][r] = 0.f;

        uint32_t aoff0 = (uint32_t)((32 * wr + (lane & 15)) * 128);
        uint32_t aoff1 = aoff0 + 16 * 128;
        uint32_t axor  = (uint32_t)((lane & 7) << 4);
        uint32_t akl   = (uint32_t)(lane & 16);

        uint32_t boff0 = (uint32_t)((40 * wc + (lane & 7) + ((lane >> 4) & 1) * 8) * 128);
        uint32_t boff1 = boff0 + 16 * 128;
        uint32_t boff2 = (uint32_t)((40 * wc + 32 + (lane & 7)) * 128);
        uint32_t bxor  = (uint32_t)((lane & 7) << 4);
        uint32_t bkl   = (uint32_t)((lane & 8) * 2);

        auto mma_stage = [&](uint32_t aBase, uint32_t bBase) {
#pragma unroll
            for (int ks = 0; ks < 4; ++ks) {
                uint32_t a[2][4];
                uint32_t kA = (uint32_t)(ks * 32) + akl;
                ldsm_x4(aBase + aoff0 + (kA ^ axor), a[0][0], a[0][1], a[0][2], a[0][3]);
                ldsm_x4(aBase + aoff1 + (kA ^ axor), a[1][0], a[1][1], a[1][2], a[1][3]);

                uint32_t kB = (uint32_t)(ks * 32) + bkl;
                uint32_t b[10];
                ldsm_x4(bBase + boff0 + (kB ^ bxor), b[0], b[1], b[2], b[3]);
                ldsm_x4(bBase + boff1 + (kB ^ bxor), b[4], b[5], b[6], b[7]);
                ldsm_x2(bBase + boff2 + (kB ^ bxor), b[8], b[9]);
#pragma unroll
                for (int mi = 0; mi < 2; mi++) {
                    mma16816(acc[mi][0], a[mi], b[0], b[1]);
                    mma16816(acc[mi][1], a[mi], b[2], b[3]);
                    mma16816(acc[mi][2], a[mi], b[4], b[5]);
                    mma16816(acc[mi][3], a[mi], b[6], b[7]);
                    mma16816(acc[mi][4], a[mi], b[8], b[9]);
                }
            }
        };

#pragma unroll 1
        for (int c = 0; c < NCHK; ++c) {
            uint32_t ah = dsm + A_OFF + (uint32_t)(c & 1) * 16384;
            uint32_t al = ah + 8192;
            int fh = 2 * c, fl = 2 * c + 1;
            uint32_t bh = dsm + (uint32_t)(fh & 3) * B_SLOT;
            uint32_t bl = dsm + (uint32_t)(fl & 3) * B_SLOT;

            mbar_wait(fullA + 8 * (c & 1), (uint32_t)((c >> 1) & 1));
            mbar_wait(fullB + 8 * (fh & 3), (uint32_t)((fh >> 2) & 1));
            mma_stage(ah, bh);             // Ah * Bh
            mma_stage(al, bh);             // Al * Bh
            __syncwarp();
            if (lane == 0) mbar_arrive(emptyB + 8 * (fh & 3));

            mbar_wait(fullB + 8 * (fl & 3), (uint32_t)((fl >> 2) & 1));
            mma_stage(ah, bl);             // Ah * Bl
            __syncwarp();
            if (lane == 0) {
                mbar_arrive(emptyB + 8 * (fl & 3));
                mbar_arrive(emptyA + 8 * (c & 1));
            }
        }

        // ---------------- epilogue: bias + LayerNorm ----------------
        int g = lane >> 2, q = lane & 3;
        float sum[4] = {0.f, 0.f, 0.f, 0.f};
        float sq[4]  = {0.f, 0.f, 0.f, 0.f};
#pragma unroll
        for (int mi = 0; mi < 2; mi++)
#pragma unroll
            for (int ni = 0; ni < 5; ni++) {
                int c0 = 40 * wc + 8 * ni + 2 * q;
                float b0 = sBias[c0], b1 = sBias[c0 + 1];
                float v0 = acc[mi][ni][0] + b0;
                float v1 = acc[mi][ni][1] + b1;
                float v2 = acc[mi][ni][2] + b0;
                float v3 = acc[mi][ni][3] + b1;
                acc[mi][ni][0] = v0; acc[mi][ni][1] = v1;
                acc[mi][ni][2] = v2; acc[mi][ni][3] = v3;
                sum[2 * mi]     += v0 + v1;  sq[2 * mi]     += v0 * v0 + v1 * v1;
                sum[2 * mi + 1] += v2 + v3;  sq[2 * mi + 1] += v2 * v2 + v3 * v3;
            }
#pragma unroll
        for (int off = 1; off <= 2; off <<= 1)
#pragma unroll
            for (int sl = 0; sl < 4; sl++) {
                sum[sl] += __shfl_xor_sync(0xffffffffu, sum[sl], off);
                sq[sl]  += __shfl_xor_sync(0xffffffffu, sq[sl],  off);
            }
        if (q == 0) {
#pragma unroll
            for (int sl = 0; sl < 4; sl++) {
                int lr = 32 * wr + 16 * (sl >> 1) + g + 8 * (sl & 1);
                sRed[wc][0][lr] = sum[sl];
                sRed[wc][1][lr] = sq[sl];
            }
        }

        __syncthreads();
        if (t < 64) {
            float S = 0.f, Q = 0.f;
#pragma unroll
            for (int k = 0; k < 8; k++) { S += sRed[k][0][t]; Q += sRed[k][1][t]; }
            float mu = S * (1.0f / OUTC);
            sMu[t]  = mu;
            sInv[t] = rsqrtf(Q * (1.0f / OUTC) - mu * mu + EPSF);
        }
        __syncthreads();

#pragma unroll
        for (int mi = 0; mi < 2; mi++) {
            int lr0 = 32 * wr + 16 * mi + g;
            int lr1 = lr0 + 8;
            float mu0 = sMu[lr0], in0 = sInv[lr0];
            float mu1 = sMu[lr1], in1 = sInv[lr1];
            float* o0 = out + (size_t)(ctaRow + lr0) * OUTC;
            float* o1 = out + (size_t)(ctaRow + lr1) * OUTC;
#pragma unroll
            for (int ni = 0; ni < 5; ni++) {
                int c0 = 40 * wc + 8 * ni + 2 * q;
                if (c0 < OUTC) {
                    float ga = sGamma[c0], gb = sGamma[c0 + 1];
                    float ba = sBeta[c0],  bb = sBeta[c0 + 1];
                    float2 r0, r1;
                    r0.x = (acc[mi][ni][0] - mu0) * in0 * ga + ba;
                    r0.y = (acc[mi][ni][1] - mu0) * in0 * gb + bb;
                    r1.x = (acc[mi][ni][2] - mu1) * in1 * ga + ba;
                    r1.y = (acc[mi][ni][3] - mu1) * in1 * gb + bb;
                    *(float2*)(o0 + c0) = r0;
                    *(float2*)(o1 + c0) = r1;
                }
            }
        }
        return;
    }

    // producers join the two epilogue barriers, no epilogue work
    __syncthreads();
    __syncthreads();
}

// ---------------------------------------------------------------------------
extern "C" void kernel_launch(void* const* d_in, const int* in_sizes, int n_in,
                              void* d_out, int out_size)
{
    const float* t1    = (const float*)d_in[0];
    const int*   ws    = (const int*)  d_in[1];
    const float* W     = (const float*)d_in[3];
    const float* blin  = (const float*)d_in[4];
    const float* gamma = (const float*)d_in[5];
    const float* beta  = (const float*)d_in[6];

    float* out = (float*)d_out;
    float* use = out + (size_t)NN * SS * OUTC;

    static bool attr_set = false;
    if (!attr_set) {
        cudaFuncSetAttribute(fused_kernel,
                             cudaFuncAttributeMaxDynamicSharedMemorySize, DYN_SMEM);
        attr_set = true;
    }

    prep_kernel<<<384, 128>>>(t1, W, use);
    fused_kernel<<<SS, 640, DYN_SMEM>>>(t1, ws, blin, gamma, beta, out);
}

// round 15
// speedup vs baseline: 1.2205x; 1.2205x over previous
#include <cuda_runtime.h>
#include <cuda_bf16.h>
#include <cstdint>

// Problem constants
#define NN   64
#define LL   1024
#define DD   512
#define LI_  1022
#define SS   127
#define OUTC 300
#define EPSF 1e-5f
#define MR   8128          // NN*SS

#define KT2  1024          // g_B row: [Bh(512) | Bl(512)]
#define NCHK 8             // 8 K-chunks of 64

// Global scratch (allocation-free rule)
__device__ __align__(128) __nv_bfloat16 g_B[(size_t)320 * KT2];

__device__ __forceinline__ uint32_t smem_u32(const void* p) {
    return (uint32_t)__cvta_generic_to_shared(p);
}
__device__ __forceinline__ void ldsm_x4(uint32_t addr, uint32_t& r0, uint32_t& r1,
                                        uint32_t& r2, uint32_t& r3) {
    asm volatile("ldmatrix.sync.aligned.m8n8.x4.shared.b16 {%0,%1,%2,%3}, [%4];"
                 : "=r"(r0), "=r"(r1), "=r"(r2), "=r"(r3) : "r"(addr));
}
__device__ __forceinline__ void ldsm_x2(uint32_t addr, uint32_t& r0, uint32_t& r1) {
    asm volatile("ldmatrix.sync.aligned.m8n8.x2.shared.b16 {%0,%1}, [%2];"
                 : "=r"(r0), "=r"(r1) : "r"(addr));
}
__device__ __forceinline__ void mma16816(float* c, const uint32_t* a,
                                         uint32_t b0, uint32_t b1) {
    asm volatile("mma.sync.aligned.m16n8k16.row.col.f32.bf16.bf16.f32 "
                 "{%0,%1,%2,%3}, {%4,%5,%6,%7}, {%8,%9}, {%0,%1,%2,%3};"
                 : "+f"(c[0]), "+f"(c[1]), "+f"(c[2]), "+f"(c[3])
                 : "r"(a[0]), "r"(a[1]), "r"(a[2]), "r"(a[3]), "r"(b0), "r"(b1));
}
__device__ __forceinline__ void cp_async16(uint32_t dst, const void* src) {
    asm volatile("cp.async.cg.shared.global [%0], [%1], 16;" :: "r"(dst), "l"(src));
}
__device__ __forceinline__ void cp_async_arrive_noinc(uint32_t mbar) {
    asm volatile("cp.async.mbarrier.arrive.noinc.shared.b64 [%0];"
                 :: "r"(mbar) : "memory");
}
__device__ __forceinline__ void mbar_init(uint32_t mbar, uint32_t cnt) {
    asm volatile("mbarrier.init.shared.b64 [%0], %1;" :: "r"(mbar), "r"(cnt) : "memory");
}
__device__ __forceinline__ void mbar_arrive(uint32_t mbar) {
    asm volatile("mbarrier.arrive.release.cta.shared::cta.b64 _, [%0];"
                 :: "r"(mbar) : "memory");
}
__device__ __forceinline__ void mbar_wait(uint32_t mbar, uint32_t parity) {
    uint32_t done;
    asm volatile("{\n\t.reg .pred p;\n\t"
                 "mbarrier.try_wait.parity.acquire.cta.shared::cta.b64 p, [%1], %2;\n\t"
                 "selp.b32 %0, 1, 0, p;\n\t}"
                 : "=r"(done) : "r"(mbar), "r"(parity) : "memory");
    if (!done) {
        asm volatile("{\n\t.reg .pred P1;\n\t"
                     "WL_%=:\n\t"
                     "mbarrier.try_wait.parity.acquire.cta.shared::cta.b64 P1, [%0], %1, 0x989680;\n\t"
                     "@P1 bra.uni WD_%=;\n\t"
                     "bra.uni WL_%=;\n\t"
                     "WD_%=:\n\t}"
                     :: "r"(mbar), "r"(parity) : "memory");
    }
}
__device__ __forceinline__ uint32_t pack_bf2(float a, float b) {
    __nv_bfloat162 p = __float22bfloat162_rn(make_float2(a, b));
    return *(uint32_t*)&p;
}
__device__ __forceinline__ void sts8(uint32_t addr, uint32_t a, uint32_t b) {
    asm volatile("st.shared.v2.b32 [%0], {%1,%2};" :: "r"(addr), "r"(a), "r"(b) : "memory");
}

// ---------------------------------------------------------------------------
// Kernel 1 (light prep): W split -> g_B [Bh|Bl] + use = t1[:,0,:] copy.
// ---------------------------------------------------------------------------
__global__ void prep_kernel(const float* __restrict__ t1,
                            const float* __restrict__ W,
                            float* __restrict__ out_use)
{
    int b  = blockIdx.x;
    int d4 = threadIdx.x;

    if (b >= 320) {
        int n = b - 320;
        ((float4*)(out_use + (size_t)n * DD))[d4] =
            ((const float4*)(t1 + (size_t)n * LL * DD))[d4];
        return;
    }
    int c  = b;
    int k4 = d4 * 4;
    __nv_bfloat16* Brow = g_B + (size_t)c * KT2;
    if (c >= OUTC) {
        uint2 z = make_uint2(0u, 0u);
        *(uint2*)(Brow + k4)       = z;
        *(uint2*)(Brow + 512 + k4) = z;
        return;
    }
    float4 wv = *(const float4*)(W + (size_t)c * DD + k4);
    __nv_bfloat16 h0 = __float2bfloat16(wv.x), h1 = __float2bfloat16(wv.y);
    __nv_bfloat16 h2 = __float2bfloat16(wv.z), h3 = __float2bfloat16(wv.w);
    __nv_bfloat16 l0 = __float2bfloat16(wv.x - __bfloat162float(h0));
    __nv_bfloat16 l1 = __float2bfloat16(wv.y - __bfloat162float(h1));
    __nv_bfloat16 l2 = __float2bfloat16(wv.z - __bfloat162float(h2));
    __nv_bfloat16 l3 = __float2bfloat16(wv.w - __bfloat162float(h3));
    __nv_bfloat16 hbuf[4] = {h0, h1, h2, h3};
    __nv_bfloat16 lbuf[4] = {l0, l1, l2, l3};
    *(uint2*)(Brow + k4)       = *(uint2*)hbuf;
    *(uint2*)(Brow + 512 + k4) = *(uint2*)lbuf;
}

// ---------------------------------------------------------------------------
// Kernel 2: fully fused, 3-role warp-specialized (rebalanced).
// 736 threads: warps 0-15  consumers (2 row x 8 col groups, 32x40/warp),
//              warp  16    B-producer (cp.async, 4-slot ring, 16 fills),
//              warps 17-22 A-producers (t1 LDG -> span means -> split-bf16
//                                       -> STS into 2-chunk A ring).
// Chunk-major: chunk c -> stages (Ah*Bh, Al*Bh, Ah*Bl).
// ---------------------------------------------------------------------------
#define B_SLOT 40960
#define A_OFF  (4 * B_SLOT)                  // 163840
#define DYN_SMEM (A_OFF + 4 * 8192)          // 196608
#define NATHR 192                            // A-producer threads (6 warps)

__global__ __launch_bounds__(736, 1)
void fused_kernel(const float* __restrict__ t1,
                  const int* __restrict__ ws32,
                  const float* __restrict__ blin,
                  const float* __restrict__ gamma,
                  const float* __restrict__ beta,
                  float* __restrict__ out)
{
    extern __shared__ __align__(1024) char dyns[];
    __shared__ __align__(8) uint64_t mbFullB[4], mbEmptyB[4], mbFullA[2], mbEmptyA[2];
    __shared__ float sBias[320], sGamma[320], sBeta[320];
    __shared__ float sRed[8][2][64];
    __shared__ float sMu[64], sInv[64];

    int t    = threadIdx.x;
    int w    = t >> 5;
    int lane = t & 31;
    int ctaRow = blockIdx.x * 64;

    uint32_t dsm    = smem_u32(dyns);
    uint32_t fullB  = smem_u32(&mbFullB[0]);
    uint32_t emptyB = smem_u32(&mbEmptyB[0]);
    uint32_t fullA  = smem_u32(&mbFullA[0]);
    uint32_t emptyA = smem_u32(&mbEmptyA[0]);

    for (int i = t; i < 320; i += 736) {
        sBias[i]  = (i < OUTC) ? blin[i]  : 0.f;
        sGamma[i] = (i < OUTC) ? gamma[i] : 0.f;
        sBeta[i]  = (i < OUTC) ? beta[i]  : 0.f;
    }
    if (t == 0) {
#pragma unroll
        for (int i = 0; i < 4; i++) {
            mbar_init(fullB + 8 * i, 32);      // 32 B-producer threads (noinc)
            mbar_init(emptyB + 8 * i, 16);     // 16 consumer warps
        }
#pragma unroll
        for (int i = 0; i < 2; i++) {
            mbar_init(fullA + 8 * i, NATHR);   // 192 A-producer threads
            mbar_init(emptyA + 8 * i, 16);
        }
    }
    __syncthreads();

    if (w >= 17) {
        // =================== A-PRODUCERS (warps 17-22, 192 threads) ========
        int pt = t - 544;                 // 0..191
        bool is64 = (ws32[1] == 0 && ws32[3] == 0);
        // tasks: j = pt + 192*i, i<6, j<1024 ; j -> (span r=j>>4, quad q=j&15)
        const float* taskPtr[6];
        int   taskCnt[6];
        float taskInv[6];
        uint32_t taskSts[6];
#pragma unroll
        for (int i = 0; i < 6; i++) {
            int j = pt + NATHR * i;
            if (j < 1024) {
                int r = j >> 4, q = j & 15;
                int gs = ctaRow + r;
                int n = gs / SS;
                long long start, end;
                if (is64) {
                    const long long* ws64 = (const long long*)ws32;
                    start = ws64[(size_t)gs * 2];
                    end   = ws64[(size_t)gs * 2 + 1];
                } else {
                    start = ws32[(size_t)gs * 2];
                    end   = ws32[(size_t)gs * 2 + 1];
                }
                if (start > (long long)(LI_ - 1)) start = LI_ - 1;
                if (end   > (long long)LI_)       end   = LI_;
                taskCnt[i] = (int)(end - start);
                taskInv[i] = 1.0f / (float)taskCnt[i];
                taskPtr[i] = t1 + ((size_t)n * LL + 1 + (size_t)start) * DD + q * 4;
                uint32_t base16 = (uint32_t)(r * 128 + (q >> 1) * 16);
                taskSts[i] = (base16 ^ ((uint32_t)(r & 7) << 4)) + (uint32_t)((q & 1) * 8);
            } else {
                taskCnt[i] = 0;
            }
        }

#pragma unroll 1
        for (int c = 0; c < NCHK; ++c) {
            if (c >= 2) mbar_wait(emptyA + 8 * (c & 1), (uint32_t)(((c >> 1) - 1) & 1));
            uint32_t ahBase = dsm + A_OFF + (uint32_t)(c & 1) * 16384;
#pragma unroll
            for (int i = 0; i < 6; i++) {
                if (taskCnt[i] == 0) continue;
                const float* p = taskPtr[i] + c * 64;
                float4 s;
                if (taskCnt[i] == 8) {
                    float4 v0 = *(const float4*)(p);
                    float4 v1 = *(const float4*)(p + DD);
                    float4 v2 = *(const float4*)(p + 2 * DD);
                    float4 v3 = *(const float4*)(p + 3 * DD);
                    float4 v4 = *(const float4*)(p + 4 * DD);
                    float4 v5 = *(const float4*)(p + 5 * DD);
                    float4 v6 = *(const float4*)(p + 6 * DD);
                    float4 v7 = *(const float4*)(p + 7 * DD);
                    v0.x += v4.x; v0.y += v4.y; v0.z += v4.z; v0.w += v4.w;
                    v1.x += v5.x; v1.y += v5.y; v1.z += v5.z; v1.w += v5.w;
                    v2.x += v6.x; v2.y += v6.y; v2.z += v6.z; v2.w += v6.w;
                    v3.x += v7.x; v3.y += v7.y; v3.z += v7.z; v3.w += v7.w;
                    v0.x += v2.x; v0.y += v2.y; v0.z += v2.z; v0.w += v2.w;
                    v1.x += v3.x; v1.y += v3.y; v1.z += v3.z; v1.w += v3.w;
                    s.x = v0.x + v1.x; s.y = v0.y + v1.y;
                    s.z = v0.z + v1.z; s.w = v0.w + v1.w;
                } else {
                    s = make_float4(0.f, 0.f, 0.f, 0.f);
                    for (int r2 = 0; r2 < taskCnt[i]; r2++) {
                        float4 a = *(const float4*)(p + (size_t)r2 * DD);
                        s.x += a.x; s.y += a.y; s.z += a.z; s.w += a.w;
                    }
                }
                float ic = taskInv[i];
                s.x *= ic; s.y *= ic; s.z *= ic; s.w *= ic;

                float h0 = __bfloat162float(__float2bfloat16(s.x));
                float h1 = __bfloat162float(__float2bfloat16(s.y));
                float h2 = __bfloat162float(__float2bfloat16(s.z));
                float h3 = __bfloat162float(__float2bfloat16(s.w));
                uint32_t hiA = pack_bf2(h0, h1), hiB = pack_bf2(h2, h3);
                uint32_t loA = pack_bf2(s.x - h0, s.y - h1);
                uint32_t loB = pack_bf2(s.z - h2, s.w - h3);

                sts8(ahBase + taskSts[i], hiA, hiB);          // Ah
                sts8(ahBase + 8192 + taskSts[i], loA, loB);   // Al
            }
            mbar_arrive(fullA + 8 * (c & 1));   // release; count = 192
        }
    } else if (w == 16) {
        // =================== B-PRODUCER (warp 16) ==========================
        int pt = t - 512;                       // 0..31
        int r0 = pt >> 3, q = pt & 7;
        const uint4* gB = (const uint4*)g_B;    // row stride 128 uint4
#pragma unroll 1
        for (int f = 0; f < 16; ++f) {
            int slot = f & 3;
            if (f >= 4) mbar_wait(emptyB + 8 * slot, (uint32_t)(((f >> 2) - 1) & 1));
            int c = f >> 1, part = f & 1;
            int bK4 = part * 64 + c * 8;
            uint32_t b_s = dsm + (uint32_t)slot * B_SLOT;
#pragma unroll 4
            for (int i = 0; i < 80; i++) {
                int row = r0 + 4 * i;
                uint32_t off = (uint32_t)(row * 128 + q * 16);
                cp_async16(b_s + (off ^ ((uint32_t)(row & 7) << 4)),
                           gB + (size_t)row * 128 + bK4 + q);
            }
            cp_async_arrive_noinc(fullB + 8 * slot);
        }
    } else {
        // =================== CONSUMERS (warps 0-15) ========================
        int wr = w & 1;        // rows 32*wr .. 32*wr+31
        int wc = w >> 1;       // cols 40*wc .. 40*wc+39

        float acc[2][5][4];
#pragma unroll
        for (int mi = 0; mi < 2; mi++)
#pragma unroll
            for (int ni = 0; ni < 5; ni++)
#pragma unroll
                for (int r = 0; r < 4; r++) acc[mi][ni][r] = 0.f;

        uint32_t aoff0 = (uint32_t)((32 * wr + (lane & 15)) * 128);
        uint32_t aoff1 = aoff0 + 16 * 128;
        uint32_t axor  = (uint32_t)((lane & 7) << 4);
        uint32_t akl   = (uint32_t)(lane & 16);

        uint32_t boff0 = (uint32_t)((40 * wc + (lane & 7) + ((lane >> 4) & 1) * 8) * 128);
        uint32_t boff1 = boff0 + 16 * 128;
        uint32_t boff2 = (uint32_t)((40 * wc + 32 + (lane & 7)) * 128);
        uint32_t bxor  = (uint32_t)((lane & 7) << 4);
        uint32_t bkl   = (uint32_t)((lane & 8) * 2);

        auto mma_stage = [&](uint32_t aBase, uint32_t bBase) {
#pragma unroll
            for (int ks = 0; ks < 4; ++ks) {
                uint32_t a[2][4];
                uint32_t kA = (uint32_t)(ks * 32) + akl;
                ldsm_x4(aBase + aoff0 + (kA ^ axor), a[0][0], a[0][1], a[0][2], a[0][3]);
                ldsm_x4(aBase + aoff1 + (kA ^ axor), a[1][0], a[1][1], a[1][2], a[1][3]);

                uint32_t kB = (uint32_t)(ks * 32) + bkl;
                uint32_t b[10];
                ldsm_x4(bBase + boff0 + (kB ^ bxor), b[0], b[1], b[2], b[3]);
                ldsm_x4(bBase + boff1 + (kB ^ bxor), b[4], b[5], b[6], b[7]);
                ldsm_x2(bBase + boff2 + (kB ^ bxor), b[8], b[9]);
#pragma unroll
                for (int mi = 0; mi < 2; mi++) {
                    mma16816(acc[mi][0], a[mi], b[0], b[1]);
                    mma16816(acc[mi][1], a[mi], b[2], b[3]);
                    mma16816(acc[mi][2], a[mi], b[4], b[5]);
                    mma16816(acc[mi][3], a[mi], b[6], b[7]);
                    mma16816(acc[mi][4], a[mi], b[8], b[9]);
                }
            }
        };

#pragma unroll 1
        for (int c = 0; c < NCHK; ++c) {
            uint32_t ah = dsm + A_OFF + (uint32_t)(c & 1) * 16384;
            uint32_t al = ah + 8192;
            int fh = 2 * c, fl = 2 * c + 1;
            uint32_t bh = dsm + (uint32_t)(fh & 3) * B_SLOT;
            uint32_t bl = dsm + (uint32_t)(fl & 3) * B_SLOT;

            mbar_wait(fullA + 8 * (c & 1), (uint32_t)((c >> 1) & 1));
            mbar_wait(fullB + 8 * (fh & 3), (uint32_t)((fh >> 2) & 1));
            mma_stage(ah, bh);             // Ah * Bh
            mma_stage(al, bh);             // Al * Bh
            __syncwarp();
            if (lane == 0) mbar_arrive(emptyB + 8 * (fh & 3));

            mbar_wait(fullB + 8 * (fl & 3), (uint32_t)((fl >> 2) & 1));
            mma_stage(ah, bl);             // Ah * Bl
            __syncwarp();
            if (lane == 0) {
                mbar_arrive(emptyB + 8 * (fl & 3));
                mbar_arrive(emptyA + 8 * (c & 1));
            }
        }

        // ---------------- epilogue: bias + LayerNorm ----------------
        int g = lane >> 2, q = lane & 3;
        float sum[4] = {0.f, 0.f, 0.f, 0.f};
        float sq[4]  = {0.f, 0.f, 0.f, 0.f};
#pragma unroll
        for (int mi = 0; mi < 2; mi++)
#pragma unroll
            for (int ni = 0; ni < 5; ni++) {
                int c0 = 40 * wc + 8 * ni + 2 * q;
                float b0 = sBias[c0], b1 = sBias[c0 + 1];
                float v0 = acc[mi][ni][0] + b0;
                float v1 = acc[mi][ni][1] + b1;
                float v2 = acc[mi][ni][2] + b0;
                float v3 = acc[mi][ni][3] + b1;
                acc[mi][ni][0] = v0; acc[mi][ni][1] = v1;
                acc[mi][ni][2] = v2; acc[mi][ni][3] = v3;
                sum[2 * mi]     += v0 + v1;  sq[2 * mi]     += v0 * v0 + v1 * v1;
                sum[2 * mi + 1] += v2 + v3;  sq[2 * mi + 1] += v2 * v2 + v3 * v3;
            }
#pragma unroll
        for (int off = 1; off <= 2; off <<= 1)
#pragma unroll
            for (int sl = 0; sl < 4; sl++) {
                sum[sl] += __shfl_xor_sync(0xffffffffu, sum[sl], off);
                sq[sl]  += __shfl_xor_sync(0xffffffffu, sq[sl],  off);
            }
        if (q == 0) {
#pragma unroll
            for (int sl = 0; sl < 4; sl++) {
                int lr = 32 * wr + 16 * (sl >> 1) + g + 8 * (sl & 1);
                sRed[wc][0][lr] = sum[sl];
                sRed[wc][1][lr] = sq[sl];
            }
        }

        __syncthreads();
        if (t < 64) {
            float S = 0.f, Q = 0.f;
#pragma unroll
            for (int k = 0; k < 8; k++) { S += sRed[k][0][t]; Q += sRed[k][1][t]; }
            float mu = S * (1.0f / OUTC);
            sMu[t]  = mu;
            sInv[t] = rsqrtf(Q * (1.0f / OUTC) - mu * mu + EPSF);
        }
        __syncthreads();

#pragma unroll
        for (int mi = 0; mi < 2; mi++) {
            int lr0 = 32 * wr + 16 * mi + g;
            int lr1 = lr0 + 8;
            float mu0 = sMu[lr0], in0 = sInv[lr0];
            float mu1 = sMu[lr1], in1 = sInv[lr1];
            float* o0 = out + (size_t)(ctaRow + lr0) * OUTC;
            float* o1 = out + (size_t)(ctaRow + lr1) * OUTC;
#pragma unroll
            for (int ni = 0; ni < 5; ni++) {
                int c0 = 40 * wc + 8 * ni + 2 * q;
                if (c0 < OUTC) {
                    float ga = sGamma[c0], gb = sGamma[c0 + 1];
                    float ba = sBeta[c0],  bb = sBeta[c0 + 1];
                    float2 r0, r1;
                    r0.x = (acc[mi][ni][0] - mu0) * in0 * ga + ba;
                    r0.y = (acc[mi][ni][1] - mu0) * in0 * gb + bb;
                    r1.x = (acc[mi][ni][2] - mu1) * in1 * ga + ba;
                    r1.y = (acc[mi][ni][3] - mu1) * in1 * gb + bb;
                    *(float2*)(o0 + c0) = r0;
                    *(float2*)(o1 + c0) = r1;
                }
            }
        }
        return;
    }

    // producers join the two epilogue barriers, no epilogue work
    __syncthreads();
    __syncthreads();
}

// ---------------------------------------------------------------------------
extern "C" void kernel_launch(void* const* d_in, const int* in_sizes, int n_in,
                              void* d_out, int out_size)
{
    const float* t1    = (const float*)d_in[0];
    const int*   ws    = (const int*)  d_in[1];
    const float* W     = (const float*)d_in[3];
    const float* blin  = (const float*)d_in[4];
    const float* gamma = (const float*)d_in[5];
    const float* beta  = (const float*)d_in[6];

    float* out = (float*)d_out;
    float* use = out + (size_t)NN * SS * OUTC;

    static bool attr_set = false;
    if (!attr_set) {
        cudaFuncSetAttribute(fused_kernel,
                             cudaFuncAttributeMaxDynamicSharedMemorySize, DYN_SMEM);
        attr_set = true;
    }

    prep_kernel<<<384, 128>>>(t1, W, use);
    fused_kernel<<<SS, 736, DYN_SMEM>>>(t1, ws, blin, gamma, beta, out);
}

// round 16
// speedup vs baseline: 1.4332x; 1.1742x over previous
#include <cuda_runtime.h>
#include <cuda_bf16.h>
#include <cstdint>

// Problem constants
#define NN   64
#define LL   1024
#define DD   512
#define LI_  1022
#define SS   127
#define OUTC 300
#define EPSF 1e-5f
#define MR   8128          // NN*SS

#define KT2  1024          // g_B row: [Bh(512) | Bl(512)]
#define NCHK 8             // 8 K-chunks of 64

// Global scratch (allocation-free rule)
__device__ __align__(128) __nv_bfloat16 g_B[(size_t)320 * KT2];

__device__ __forceinline__ uint32_t smem_u32(const void* p) {
    return (uint32_t)__cvta_generic_to_shared(p);
}
__device__ __forceinline__ void ldsm_x4(uint32_t addr, uint32_t& r0, uint32_t& r1,
                                        uint32_t& r2, uint32_t& r3) {
    asm volatile("ldmatrix.sync.aligned.m8n8.x4.shared.b16 {%0,%1,%2,%3}, [%4];"
                 : "=r"(r0), "=r"(r1), "=r"(r2), "=r"(r3) : "r"(addr));
}
__device__ __forceinline__ void ldsm_x2(uint32_t addr, uint32_t& r0, uint32_t& r1) {
    asm volatile("ldmatrix.sync.aligned.m8n8.x2.shared.b16 {%0,%1}, [%2];"
                 : "=r"(r0), "=r"(r1) : "r"(addr));
}
__device__ __forceinline__ void mma16816(float* c, const uint32_t* a,
                                         uint32_t b0, uint32_t b1) {
    asm volatile("mma.sync.aligned.m16n8k16.row.col.f32.bf16.bf16.f32 "
                 "{%0,%1,%2,%3}, {%4,%5,%6,%7}, {%8,%9}, {%0,%1,%2,%3};"
                 : "+f"(c[0]), "+f"(c[1]), "+f"(c[2]), "+f"(c[3])
                 : "r"(a[0]), "r"(a[1]), "r"(a[2]), "r"(a[3]), "r"(b0), "r"(b1));
}
__device__ __forceinline__ void cp_async16(uint32_t dst, const void* src) {
    asm volatile("cp.async.cg.shared.global [%0], [%1], 16;" :: "r"(dst), "l"(src));
}
#define CP_COMMIT() asm volatile("cp.async.commit_group;")
#define CP_WAIT1()  asm volatile("cp.async.wait_group 1;" ::: "memory")

__device__ __forceinline__ uint32_t pack_bf2(float a, float b) {
    __nv_bfloat162 p = __float22bfloat162_rn(make_float2(a, b));
    return *(uint32_t*)&p;
}
__device__ __forceinline__ void sts16(uint32_t addr, uint32_t a, uint32_t b,
                                      uint32_t c, uint32_t d) {
    asm volatile("st.shared.v4.b32 [%0], {%1,%2,%3,%4};"
                 :: "r"(addr), "r"(a), "r"(b), "r"(c), "r"(d) : "memory");
}

// ---------------------------------------------------------------------------
// Kernel 1 (light prep): W split -> g_B [Bh|Bl] + use = t1[:,0,:] copy.
// grid = 384: b<320 W rows; b>=320 use rows. 128 threads.
// ---------------------------------------------------------------------------
__global__ void prep_kernel(const float* __restrict__ t1,
                            const float* __restrict__ W,
                            float* __restrict__ out_use)
{
    int b  = blockIdx.x;
    int d4 = threadIdx.x;

    if (b >= 320) {
        int n = b - 320;
        ((float4*)(out_use + (size_t)n * DD))[d4] =
            ((const float4*)(t1 + (size_t)n * LL * DD))[d4];
        return;
    }
    int c  = b;
    int k4 = d4 * 4;
    __nv_bfloat16* Brow = g_B + (size_t)c * KT2;
    if (c >= OUTC) {
        uint2 z = make_uint2(0u, 0u);
        *(uint2*)(Brow + k4)       = z;
        *(uint2*)(Brow + 512 + k4) = z;
        return;
    }
    float4 wv = *(const float4*)(W + (size_t)c * DD + k4);
    __nv_bfloat16 h0 = __float2bfloat16(wv.x), h1 = __float2bfloat16(wv.y);
    __nv_bfloat16 h2 = __float2bfloat16(wv.z), h3 = __float2bfloat16(wv.w);
    __nv_bfloat16 l0 = __float2bfloat16(wv.x - __bfloat162float(h0));
    __nv_bfloat16 l1 = __float2bfloat16(wv.y - __bfloat162float(h1));
    __nv_bfloat16 l2 = __float2bfloat16(wv.z - __bfloat162float(h2));
    __nv_bfloat16 l3 = __float2bfloat16(wv.w - __bfloat162float(h3));
    __nv_bfloat16 hbuf[4] = {h0, h1, h2, h3};
    __nv_bfloat16 lbuf[4] = {l0, l1, l2, l3};
    *(uint2*)(Brow + k4)       = *(uint2*)hbuf;
    *(uint2*)(Brow + 512 + k4) = *(uint2*)lbuf;
}

// ---------------------------------------------------------------------------
// Kernel 2: fused, PHASE-SEPARATED per CTA.
//  Phase 1: all 512 threads produce the CTA's full split-bf16 A (128 KB)
//           in smem from t1 span means. B fills for chunk 0 issued first.
//  Phase 2: R12-proven HMMA loop (16 warps, 2 row x 8 col groups, 32x40),
//           A resident, B double-buffered (slot0=Bh, slot1=Bl) via cp.async.
//  Chunk-major: chunk c -> stages (Ah*Bh, Al*Bh, Ah*Bl).
// ---------------------------------------------------------------------------
#define B_SLOT 40960
#define A_OFF  (2 * B_SLOT)                   // 81920
#define DYN_SMEM (A_OFF + 131072)             // 212992 (A: 8 chunks x 16KB)

__global__ __launch_bounds__(512, 1)
void fused_kernel(const float* __restrict__ t1,
                  const int* __restrict__ ws32,
                  const float* __restrict__ blin,
                  const float* __restrict__ gamma,
                  const float* __restrict__ beta,
                  float* __restrict__ out)
{
    extern __shared__ __align__(1024) char dyns[];
    __shared__ float sBias[320], sGamma[320], sBeta[320];
    __shared__ float sRed[8][2][64];
    __shared__ float sMu[64], sInv[64];

    int t    = threadIdx.x;
    int w    = t >> 5;
    int lane = t & 31;
    int ctaRow = blockIdx.x * 64;

    uint32_t dsm = smem_u32(dyns);

    for (int i = t; i < 320; i += 512) {
        sBias[i]  = (i < OUTC) ? blin[i]  : 0.f;
        sGamma[i] = (i < OUTC) ? gamma[i] : 0.f;
        sBeta[i]  = (i < OUTC) ? beta[i]  : 0.f;
    }

    // ---- B fill helper (all 512 threads; 5 x 16B each) ----
    const uint4* gB = (const uint4*)g_B;    // row stride 128 uint4
    int brow_s[5], bq_s[5];
#pragma unroll
    for (int i = 0; i < 5; i++) {
        int idx = t + 512 * i;
        brow_s[i] = idx >> 3; bq_s[i] = idx & 7;
    }
    auto issueB = [&](int f) {              // f = 2c + part ; slot = f&1
        int c = f >> 1, part = f & 1;
        int bK4 = part * 64 + c * 8;
        uint32_t b_s = dsm + (uint32_t)(f & 1) * B_SLOT;
#pragma unroll
        for (int i = 0; i < 5; i++) {
            uint32_t off = (uint32_t)(brow_s[i] * 128 + bq_s[i] * 16);
            cp_async16(b_s + (off ^ ((uint32_t)(brow_s[i] & 7) << 4)),
                       gB + (size_t)brow_s[i] * 128 + bK4 + bq_s[i]);
        }
        CP_COMMIT();
    };

    // B prologue: Bh0 (g1), Bl0 (g2) — land during phase 1 for free
    issueB(0);
    issueB(1);

    // =================== PHASE 1: produce A in smem ===================
    {
        int r = t >> 3, q = t & 7;          // span r, 8-float slot q
        int gs = ctaRow + r;
        int n  = gs / SS;
        bool is64 = (ws32[1] == 0 && ws32[3] == 0);
        long long start, end;
        if (is64) {
            const long long* ws64 = (const long long*)ws32;
            start = ws64[(size_t)gs * 2];
            end   = ws64[(size_t)gs * 2 + 1];
        } else {
            start = ws32[(size_t)gs * 2];
            end   = ws32[(size_t)gs * 2 + 1];
        }
        if (start > (long long)(LI_ - 1)) start = LI_ - 1;
        if (end   > (long long)LI_)       end   = LI_;
        int cnt = (int)(end - start);
        float ic = 1.0f / (float)cnt;
        const float* rowPtr =
            t1 + ((size_t)n * LL + 1 + (size_t)start) * DD + q * 8;
        uint32_t aSwz = ((uint32_t)(r * 128 + q * 16)) ^ ((uint32_t)(r & 7) << 4);

#pragma unroll 1
        for (int c = 0; c < NCHK; ++c) {
            const float* p = rowPtr + c * 64;
            float4 s0, s1;
            if (cnt == 8) {
                float4 a[8], b[8];
#pragma unroll
                for (int r2 = 0; r2 < 8; r2++) {
                    a[r2] = *(const float4*)(p + (size_t)r2 * DD);
                    b[r2] = *(const float4*)(p + (size_t)r2 * DD + 4);
                }
#pragma unroll
                for (int r2 = 4; r2 < 8; r2++) {
                    a[r2 - 4].x += a[r2].x; a[r2 - 4].y += a[r2].y;
                    a[r2 - 4].z += a[r2].z; a[r2 - 4].w += a[r2].w;
                    b[r2 - 4].x += b[r2].x; b[r2 - 4].y += b[r2].y;
                    b[r2 - 4].z += b[r2].z; b[r2 - 4].w += b[r2].w;
                }
                a[0].x += a[2].x; a[0].y += a[2].y; a[0].z += a[2].z; a[0].w += a[2].w;
                a[1].x += a[3].x; a[1].y += a[3].y; a[1].z += a[3].z; a[1].w += a[3].w;
                b[0].x += b[2].x; b[0].y += b[2].y; b[0].z += b[2].z; b[0].w += b[2].w;
                b[1].x += b[3].x; b[1].y += b[3].y; b[1].z += b[3].z; b[1].w += b[3].w;
                s0.x = a[0].x + a[1].x; s0.y = a[0].y + a[1].y;
                s0.z = a[0].z + a[1].z; s0.w = a[0].w + a[1].w;
                s1.x = b[0].x + b[1].x; s1.y = b[0].y + b[1].y;
                s1.z = b[0].z + b[1].z; s1.w = b[0].w + b[1].w;
            } else {
                s0 = make_float4(0.f, 0.f, 0.f, 0.f);
                s1 = make_float4(0.f, 0.f, 0.f, 0.f);
                for (int r2 = 0; r2 < cnt; r2++) {
                    float4 a = *(const float4*)(p + (size_t)r2 * DD);
                    float4 b = *(const float4*)(p + (size_t)r2 * DD + 4);
                    s0.x += a.x; s0.y += a.y; s0.z += a.z; s0.w += a.w;
                    s1.x += b.x; s1.y += b.y; s1.z += b.z; s1.w += b.w;
                }
            }
            s0.x *= ic; s0.y *= ic; s0.z *= ic; s0.w *= ic;
            s1.x *= ic; s1.y *= ic; s1.z *= ic; s1.w *= ic;

            float h0 = __bfloat162float(__float2bfloat16(s0.x));
            float h1 = __bfloat162float(__float2bfloat16(s0.y));
            float h2 = __bfloat162float(__float2bfloat16(s0.z));
            float h3 = __bfloat162float(__float2bfloat16(s0.w));
            float h4 = __bfloat162float(__float2bfloat16(s1.x));
            float h5 = __bfloat162float(__float2bfloat16(s1.y));
            float h6 = __bfloat162float(__float2bfloat16(s1.z));
            float h7 = __bfloat162float(__float2bfloat16(s1.w));

            uint32_t ahBase = dsm + A_OFF + (uint32_t)c * 16384;
            sts16(ahBase + aSwz,
                  pack_bf2(h0, h1), pack_bf2(h2, h3),
                  pack_bf2(h4, h5), pack_bf2(h6, h7));
            sts16(ahBase + 8192 + aSwz,
                  pack_bf2(s0.x - h0, s0.y - h1), pack_bf2(s0.z - h2, s0.w - h3),
                  pack_bf2(s1.x - h4, s1.y - h5), pack_bf2(s1.z - h6, s1.w - h7));
        }
    }
    __syncthreads();    // A fully resident

    // =================== PHASE 2: HMMA + LayerNorm ===================
    int wr = w & 1;        // rows 32*wr .. 32*wr+31
    int wc = w >> 1;       // cols 40*wc .. 40*wc+39

    float acc[2][5][4];
#pragma unroll
    for (int mi = 0; mi < 2; mi++)
#pragma unroll
        for (int ni = 0; ni < 5; ni++)
#pragma unroll
            for (int r = 0; r < 4; r++) acc[mi][ni][r] = 0.f;

    uint32_t aoff0 = (uint32_t)((32 * wr + (lane & 15)) * 128);
    uint32_t aoff1 = aoff0 + 16 * 128;
    uint32_t axor  = (uint32_t)((lane & 7) << 4);
    uint32_t akl   = (uint32_t)(lane & 16);

    uint32_t boff0 = (uint32_t)((40 * wc + (lane & 7) + ((lane >> 4) & 1) * 8) * 128);
    uint32_t boff1 = boff0 + 16 * 128;
    uint32_t boff2 = (uint32_t)((40 * wc + 32 + (lane & 7)) * 128);
    uint32_t bxor  = (uint32_t)((lane & 7) << 4);
    uint32_t bkl   = (uint32_t)((lane & 8) * 2);

    auto mma_stage = [&](uint32_t aBase, uint32_t bBase) {
#pragma unroll
        for (int ks = 0; ks < 4; ++ks) {
            uint32_t a[2][4];
            uint32_t kA = (uint32_t)(ks * 32) + akl;
            ldsm_x4(aBase + aoff0 + (kA ^ axor), a[0][0], a[0][1], a[0][2], a[0][3]);
            ldsm_x4(aBase + aoff1 + (kA ^ axor), a[1][0], a[1][1], a[1][2], a[1][3]);

            uint32_t kB = (uint32_t)(ks * 32) + bkl;
            uint32_t b[10];
            ldsm_x4(bBase + boff0 + (kB ^ bxor), b[0], b[1], b[2], b[3]);
            ldsm_x4(bBase + boff1 + (kB ^ bxor), b[4], b[5], b[6], b[7]);
            ldsm_x2(bBase + boff2 + (kB ^ bxor), b[8], b[9]);
#pragma unroll
            for (int mi = 0; mi < 2; mi++) {
                mma16816(acc[mi][0], a[mi], b[0], b[1]);
                mma16816(acc[mi][1], a[mi], b[2], b[3]);
                mma16816(acc[mi][2], a[mi], b[4], b[5]);
                mma16816(acc[mi][3], a[mi], b[6], b[7]);
                mma16816(acc[mi][4], a[mi], b[8], b[9]);
            }
        }
    };

#pragma unroll 1
    for (int c = 0; c < NCHK; ++c) {
        uint32_t ah = dsm + A_OFF + (uint32_t)c * 16384;
        uint32_t al = ah + 8192;
        uint32_t bh = dsm;              // slot 0
        uint32_t bl = dsm + B_SLOT;     // slot 1

        CP_WAIT1();                     // Bh[c] resident (pending <= Bl[c]/next)
        __syncthreads();
        mma_stage(ah, bh);              // Ah * Bh
        mma_stage(al, bh);              // Al * Bh
        __syncthreads();                // all done reading slot 0
        if (c + 1 < NCHK) issueB(2 * (c + 1));
        else              CP_COMMIT();

        CP_WAIT1();                     // Bl[c] resident
        __syncthreads();
        mma_stage(ah, bl);              // Ah * Bl
        __syncthreads();                // all done reading slot 1
        if (c + 1 < NCHK) issueB(2 * (c + 1) + 1);
        else              CP_COMMIT();
    }

    // ---------------- epilogue: bias + LayerNorm ----------------
    int g = lane >> 2, q = lane & 3;
    float sum[4] = {0.f, 0.f, 0.f, 0.f};
    float sq[4]  = {0.f, 0.f, 0.f, 0.f};
#pragma unroll
    for (int mi = 0; mi < 2; mi++)
#pragma unroll
        for (int ni = 0; ni < 5; ni++) {
            int c0 = 40 * wc + 8 * ni + 2 * q;
            float b0 = sBias[c0], b1 = sBias[c0 + 1];
            float v0 = acc[mi][ni][0] + b0;
            float v1 = acc[mi][ni][1] + b1;
            float v2 = acc[mi][ni][2] + b0;
            float v3 = acc[mi][ni][3] + b1;
            acc[mi][ni][0] = v0; acc[mi][ni][1] = v1;
            acc[mi][ni][2] = v2; acc[mi][ni][3] = v3;
            sum[2 * mi]     += v0 + v1;  sq[2 * mi]     += v0 * v0 + v1 * v1;
            sum[2 * mi + 1] += v2 + v3;  sq[2 * mi + 1] += v2 * v2 + v3 * v3;
        }
#pragma unroll
    for (int off = 1; off <= 2; off <<= 1)
#pragma unroll
        for (int sl = 0; sl < 4; sl++) {
            sum[sl] += __shfl_xor_sync(0xffffffffu, sum[sl], off);
            sq[sl]  += __shfl_xor_sync(0xffffffffu, sq[sl],  off);
        }
    if (q == 0) {
#pragma unroll
        for (int sl = 0; sl < 4; sl++) {
            int lr = 32 * wr + 16 * (sl >> 1) + g + 8 * (sl & 1);
            sRed[wc][0][lr] = sum[sl];
            sRed[wc][1][lr] = sq[sl];
        }
    }
    __syncthreads();
    if (t < 64) {
        float S = 0.f, Q = 0.f;
#pragma unroll
        for (int k = 0; k < 8; k++) { S += sRed[k][0][t]; Q += sRed[k][1][t]; }
        float mu = S * (1.0f / OUTC);
        sMu[t]  = mu;
        sInv[t] = rsqrtf(Q * (1.0f / OUTC) - mu * mu + EPSF);
    }
    __syncthreads();

#pragma unroll
    for (int mi = 0; mi < 2; mi++) {
        int lr0 = 32 * wr + 16 * mi + g;
        int lr1 = lr0 + 8;
        float mu0 = sMu[lr0], in0 = sInv[lr0];
        float mu1 = sMu[lr1], in1 = sInv[lr1];
        float* o0 = out + (size_t)(ctaRow + lr0) * OUTC;
        float* o1 = out + (size_t)(ctaRow + lr1) * OUTC;
#pragma unroll
        for (int ni = 0; ni < 5; ni++) {
            int c0 = 40 * wc + 8 * ni + 2 * q;
            if (c0 < OUTC) {
                float ga = sGamma[c0], gb = sGamma[c0 + 1];
                float ba = sBeta[c0],  bb = sBeta[c0 + 1];
                float2 r0, r1;
                r0.x = (acc[mi][ni][0] - mu0) * in0 * ga + ba;
                r0.y = (acc[mi][ni][1] - mu0) * in0 * gb + bb;
                r1.x = (acc[mi][ni][2] - mu1) * in1 * ga + ba;
                r1.y = (acc[mi][ni][3] - mu1) * in1 * gb + bb;
                *(float2*)(o0 + c0) = r0;
                *(float2*)(o1 + c0) = r1;
            }
        }
    }
}

// ---------------------------------------------------------------------------
extern "C" void kernel_launch(void* const* d_in, const int* in_sizes, int n_in,
                              void* d_out, int out_size)
{
    const float* t1    = (const float*)d_in[0];
    const int*   ws    = (const int*)  d_in[1];
    const float* W     = (const float*)d_in[3];
    const float* blin  = (const float*)d_in[4];
    const float* gamma = (const float*)d_in[5];
    const float* beta  = (const float*)d_in[6];

    float* out = (float*)d_out;
    float* use = out + (size_t)NN * SS * OUTC;

    static bool attr_set = false;
    if (!attr_set) {
        cudaFuncSetAttribute(fused_kernel,
                             cudaFuncAttributeMaxDynamicSharedMemorySize, DYN_SMEM);
        attr_set = true;
    }

    prep_kernel<<<384, 128>>>(t1, W, use);
    fused_kernel<<<SS, 512, DYN_SMEM>>>(t1, ws, blin, gamma, beta, out);
}

// round 17
// speedup vs baseline: 1.9063x; 1.3302x over previous
#include <cuda_runtime.h>
#include <cuda_bf16.h>
#include <cstdint>

// Problem constants
#define NN   64
#define LL   1024
#define DD   512
#define LI_  1022
#define SS   127
#define OUTC 300
#define EPSF 1e-5f

#define KT2  1024          // dedup: [hi|lo]
#define NCHK 8             // 8 K-chunks of 64
#define MR   8128          // NN*SS

// Global scratch (allocation-free rule)
__device__ __align__(128) __nv_bfloat16 g_A[(size_t)MR * KT2];   // [Ah|Al]
__device__ __align__(128) __nv_bfloat16 g_B[(size_t)320 * KT2];  // [Bh|Bl]

__device__ __forceinline__ uint32_t smem_u32(const void* p) {
    return (uint32_t)__cvta_generic_to_shared(p);
}
__device__ __forceinline__ void ldsm_x4(uint32_t addr, uint32_t& r0, uint32_t& r1,
                                        uint32_t& r2, uint32_t& r3) {
    asm volatile("ldmatrix.sync.aligned.m8n8.x4.shared.b16 {%0,%1,%2,%3}, [%4];"
                 : "=r"(r0), "=r"(r1), "=r"(r2), "=r"(r3) : "r"(addr));
}
__device__ __forceinline__ void ldsm_x2(uint32_t addr, uint32_t& r0, uint32_t& r1) {
    asm volatile("ldmatrix.sync.aligned.m8n8.x2.shared.b16 {%0,%1}, [%2];"
                 : "=r"(r0), "=r"(r1) : "r"(addr));
}
__device__ __forceinline__ void mma16816(float* c, const uint32_t* a,
                                         uint32_t b0, uint32_t b1) {
    asm volatile("mma.sync.aligned.m16n8k16.row.col.f32.bf16.bf16.f32 "
                 "{%0,%1,%2,%3}, {%4,%5,%6,%7}, {%8,%9}, {%0,%1,%2,%3};"
                 : "+f"(c[0]), "+f"(c[1]), "+f"(c[2]), "+f"(c[3])
                 : "r"(a[0]), "r"(a[1]), "r"(a[2]), "r"(a[3]), "r"(b0), "r"(b1));
}
__device__ __forceinline__ void cp_async16(uint32_t dst, const void* src) {
    asm volatile("cp.async.cg.shared.global [%0], [%1], 16;" :: "r"(dst), "l"(src));
}
#define CP_COMMIT() asm volatile("cp.async.commit_group;")
#define CP_WAIT1()  asm volatile("cp.async.wait_group 1;" ::: "memory")

// ---------------------------------------------------------------------------
// Kernel 1: fused  (a) span means -> split-bf16 g_A rows [Ah|Al] + `use` copy
//                  (b) W split    -> g_B rows [Bh|Bl]
// grid = 8448: blocks [0,8128) = means, [8128,8448) = W rows. 128 threads.
// ---------------------------------------------------------------------------
__global__ void prep_kernel(const float* __restrict__ t1,
                            const int* __restrict__ ws32,
                            const float* __restrict__ W,
                            float* __restrict__ out_use)
{
    int b  = blockIdx.x;
    int d4 = threadIdx.x;

    if (b >= MR) {                       // ---- W split path ----
        int c  = b - MR;
        int k4 = d4 * 4;
        __nv_bfloat16* Brow = g_B + (size_t)c * KT2;
        if (c >= OUTC) {
            uint2 z = make_uint2(0u, 0u);
            *(uint2*)(Brow + k4)       = z;
            *(uint2*)(Brow + 512 + k4) = z;
            return;
        }
        float4 wv = *(const float4*)(W + (size_t)c * DD + k4);
        __nv_bfloat16 h0 = __float2bfloat16(wv.x), h1 = __float2bfloat16(wv.y);
        __nv_bfloat16 h2 = __float2bfloat16(wv.z), h3 = __float2bfloat16(wv.w);
        __nv_bfloat16 l0 = __float2bfloat16(wv.x - __bfloat162float(h0));
        __nv_bfloat16 l1 = __float2bfloat16(wv.y - __bfloat162float(h1));
        __nv_bfloat16 l2 = __float2bfloat16(wv.z - __bfloat162float(h2));
        __nv_bfloat16 l3 = __float2bfloat16(wv.w - __bfloat162float(h3));
        __nv_bfloat16 hbuf[4] = {h0, h1, h2, h3};
        __nv_bfloat16 lbuf[4] = {l0, l1, l2, l3};
        *(uint2*)(Brow + k4)       = *(uint2*)hbuf;
        *(uint2*)(Brow + 512 + k4) = *(uint2*)lbuf;
        return;
    }

    // ---- means path ----
    __nv_bfloat16* Arow = g_A + (size_t)b * KT2;
    int n = b / SS;
    int s = b - n * SS;

    bool is64 = (ws32[1] == 0 && ws32[3] == 0);
    long long start, end;
    if (is64) {
        const long long* ws64 = (const long long*)ws32;
        start = ws64[(size_t)(n * SS + s) * 2];
        end   = ws64[(size_t)(n * SS + s) * 2 + 1];
    } else {
        start = ws32[(size_t)(n * SS + s) * 2];
        end   = ws32[(size_t)(n * SS + s) * 2 + 1];
    }
    if (start > (long long)(LI_ - 1)) start = LI_ - 1;
    if (end   > (long long)LI_)       end   = LI_;
    int cnt = (int)(end - start);

    const float4* base =
        (const float4*)(t1 + ((size_t)n * LL + 1 + (size_t)start) * DD) + d4;

    float4 acc = make_float4(0.f, 0.f, 0.f, 0.f);
    if (cnt == 8) {
        float4 v[8];
#pragma unroll
        for (int r = 0; r < 8; ++r) v[r] = base[(size_t)r * (DD / 4)];
#pragma unroll
        for (int r = 0; r < 8; ++r) {
            acc.x += v[r].x; acc.y += v[r].y; acc.z += v[r].z; acc.w += v[r].w;
        }
    } else {
        for (int r = 0; r < cnt; ++r) {
            float4 v = base[(size_t)r * (DD / 4)];
            acc.x += v.x; acc.y += v.y; acc.z += v.z; acc.w += v.w;
        }
    }
    float inv = 1.0f / (float)cnt;
    acc.x *= inv; acc.y *= inv; acc.z *= inv; acc.w *= inv;

    __nv_bfloat16 h0 = __float2bfloat16(acc.x), h1 = __float2bfloat16(acc.y);
    __nv_bfloat16 h2 = __float2bfloat16(acc.z), h3 = __float2bfloat16(acc.w);
    __nv_bfloat16 l0 = __float2bfloat16(acc.x - __bfloat162float(h0));
    __nv_bfloat16 l1 = __float2bfloat16(acc.y - __bfloat162float(h1));
    __nv_bfloat16 l2 = __float2bfloat16(acc.z - __bfloat162float(h2));
    __nv_bfloat16 l3 = __float2bfloat16(acc.w - __bfloat162float(h3));
    __nv_bfloat16 hbuf[4] = {h0, h1, h2, h3};
    __nv_bfloat16 lbuf[4] = {l0, l1, l2, l3};
    *(uint2*)(Arow + 4 * d4)       = *(uint2*)hbuf;   // Ah
    *(uint2*)(Arow + 512 + 4 * d4) = *(uint2*)lbuf;   // Al

    if (s == 0) {
        ((float4*)(out_use + (size_t)n * DD))[d4] =
            ((const float4*)(t1 + (size_t)n * LL * DD))[d4];
    }
}

// ---------------------------------------------------------------------------
// Kernel 2: HMMA GEMM, 3-term-FUSED inner loop + fused LayerNorm.
// grid = 127 CTAs (64 rows), 512 threads (16 warps: 2 row x 8 col groups,
// warp tile 32x40).  Chunk-major 2-deep ring: slot = [Ah 8K|Al 8K|Bh 40K|Bl 40K].
// Per ks: load ah,al,bh,bl fragments ONCE -> 30 mma (Ah*Bh + Al*Bh + Ah*Bl).
// ---------------------------------------------------------------------------
#define SLOT_BYTES 98304            // 8192+8192+40960+40960
#define DYN_SMEM (2 * SLOT_BYTES)   // 196608
#define OFF_AL 8192
#define OFF_BH 16384
#define OFF_BL 57344

__global__ __launch_bounds__(512, 1)
void gemm_ln_kernel(const float* __restrict__ blin,
                    const float* __restrict__ gamma,
                    const float* __restrict__ beta,
                    float* __restrict__ out)
{
    extern __shared__ __align__(1024) char dyns[];
    __shared__ float sBias[320], sGamma[320], sBeta[320];
    __shared__ float sRed[8][2][64];
    __shared__ float sMu[64], sInv[64];

    int t    = threadIdx.x;
    int w    = t >> 5;
    int lane = t & 31;
    int wr   = w & 1;        // rows 32*wr .. 32*wr+31
    int wc   = w >> 1;       // cols 40*wc .. 40*wc+39
    int ctaRow = blockIdx.x * 64;

    uint32_t dsm = smem_u32(dyns);

    for (int i = t; i < 320; i += 512) {
        sBias[i]  = (i < OUTC) ? blin[i]  : 0.f;
        sGamma[i] = (i < OUTC) ? gamma[i] : 0.f;
        sBeta[i]  = (i < OUTC) ? beta[i]  : 0.f;
    }

    float acc[2][5][4];
#pragma unroll
    for (int mi = 0; mi < 2; mi++)
#pragma unroll
        for (int ni = 0; ni < 5; ni++)
#pragma unroll
            for (int r = 0; r < 4; r++) acc[mi][ni][r] = 0.f;

    // ldmatrix per-thread constants (proven R12 maps)
    uint32_t aoff0 = (uint32_t)((32 * wr + (lane & 15)) * 128);
    uint32_t aoff1 = aoff0 + 16 * 128;
    uint32_t axor  = (uint32_t)((lane & 7) << 4);
    uint32_t akl   = (uint32_t)(lane & 16);

    uint32_t boff0 = (uint32_t)((40 * wc + (lane & 7) + ((lane >> 4) & 1) * 8) * 128);
    uint32_t boff1 = boff0 + 16 * 128;
    uint32_t boff2 = (uint32_t)((40 * wc + 32 + (lane & 7)) * 128);
    uint32_t bxor  = (uint32_t)((lane & 7) << 4);
    uint32_t bkl   = (uint32_t)((lane & 8) * 2);

    // staging maps (per chunk): A 1 item each for h/l, B 5 items each for h/l
    const uint4* gA = (const uint4*)(g_A + (size_t)ctaRow * KT2);   // row stride 128 u4
    const uint4* gB = (const uint4*)g_B;

    int arow_s = t >> 3, aq_s = t & 7;
    int brow_s[5], bq_s[5];
#pragma unroll
    for (int i = 0; i < 5; i++) {
        int idx = t + 512 * i;
        brow_s[i] = idx >> 3; bq_s[i] = idx & 7;
    }

    auto issue_chunk = [&](int c) {
        uint32_t base = dsm + (uint32_t)(c & 1) * SLOT_BYTES;
        int k4 = c * 8;                       // uint4 offset within hi segment
        // A (h and l)
        {
            uint32_t off = (uint32_t)(arow_s * 128 + aq_s * 16);
            uint32_t sw = off ^ ((uint32_t)(arow_s & 7) << 4);
            const uint4* src = gA + (size_t)arow_s * 128 + k4 + aq_s;
            cp_async16(base + sw, src);               // Ah
            cp_async16(base + OFF_AL + sw, src + 64); // Al
        }
        // B (h and l)
#pragma unroll
        for (int i = 0; i < 5; i++) {
            uint32_t off = (uint32_t)(brow_s[i] * 128 + bq_s[i] * 16);
            uint32_t sw = off ^ ((uint32_t)(brow_s[i] & 7) << 4);
            const uint4* src = gB + (size_t)brow_s[i] * 128 + k4 + bq_s[i];
            cp_async16(base + OFF_BH + sw, src);        // Bh
            cp_async16(base + OFF_BL + sw, src + 64);   // Bl
        }
        CP_COMMIT();
    };

    // prologue: chunks 0 and 1 in flight
    issue_chunk(0);
    issue_chunk(1);

#pragma unroll 1
    for (int c = 0; c < NCHK; ++c) {
        CP_WAIT1();              // chunk c resident (pending <= 1: chunk c+1)
        __syncthreads();

        uint32_t base = dsm + (uint32_t)(c & 1) * SLOT_BYTES;
        uint32_t ahB = base, alB = base + OFF_AL;
        uint32_t bhB = base + OFF_BH, blB = base + OFF_BL;

#pragma unroll
        for (int ks = 0; ks < 4; ++ks) {
            uint32_t kA = (uint32_t)(ks * 32) + akl;
            uint32_t kB = (uint32_t)(ks * 32) + bkl;
            uint32_t ah[2][4], al[2][4];
            ldsm_x4(ahB + aoff0 + (kA ^ axor), ah[0][0], ah[0][1], ah[0][2], ah[0][3]);
            ldsm_x4(ahB + aoff1 + (kA ^ axor), ah[1][0], ah[1][1], ah[1][2], ah[1][3]);
            ldsm_x4(alB + aoff0 + (kA ^ axor), al[0][0], al[0][1], al[0][2], al[0][3]);
            ldsm_x4(alB + aoff1 + (kA ^ axor), al[1][0], al[1][1], al[1][2], al[1][3]);

            uint32_t bh[10], bl[10];
            ldsm_x4(bhB + boff0 + (kB ^ bxor), bh[0], bh[1], bh[2], bh[3]);
            ldsm_x4(bhB + boff1 + (kB ^ bxor), bh[4], bh[5], bh[6], bh[7]);
            ldsm_x2(bhB + boff2 + (kB ^ bxor), bh[8], bh[9]);
            ldsm_x4(blB + boff0 + (kB ^ bxor), bl[0], bl[1], bl[2], bl[3]);
            ldsm_x4(blB + boff1 + (kB ^ bxor), bl[4], bl[5], bl[6], bl[7]);
            ldsm_x2(blB + boff2 + (kB ^ bxor), bl[8], bl[9]);

#pragma unroll
            for (int mi = 0; mi < 2; mi++) {
#pragma unroll
                for (int ni = 0; ni < 5; ni++) {
                    mma16816(acc[mi][ni], ah[mi], bh[2 * ni], bh[2 * ni + 1]);
                    mma16816(acc[mi][ni], al[mi], bh[2 * ni], bh[2 * ni + 1]);
                    mma16816(acc[mi][ni], ah[mi], bl[2 * ni], bl[2 * ni + 1]);
                }
            }
        }

        __syncthreads();         // all warps done reading slot c
        if (c + 2 < NCHK) issue_chunk(c + 2);
        else              CP_COMMIT();      // keep group count telescoping
    }

    // ---------------- epilogue: bias + LayerNorm ----------------
    int g = lane >> 2, q = lane & 3;

    float sum[4] = {0.f, 0.f, 0.f, 0.f};
    float sq[4]  = {0.f, 0.f, 0.f, 0.f};
#pragma unroll
    for (int mi = 0; mi < 2; mi++)
#pragma unroll
        for (int ni = 0; ni < 5; ni++) {
            int c0 = 40 * wc + 8 * ni + 2 * q;
            float b0 = sBias[c0], b1 = sBias[c0 + 1];
            float v0 = acc[mi][ni][0] + b0;
            float v1 = acc[mi][ni][1] + b1;
            float v2 = acc[mi][ni][2] + b0;
            float v3 = acc[mi][ni][3] + b1;
            acc[mi][ni][0] = v0; acc[mi][ni][1] = v1;
            acc[mi][ni][2] = v2; acc[mi][ni][3] = v3;
            sum[2 * mi]     += v0 + v1;  sq[2 * mi]     += v0 * v0 + v1 * v1;
            sum[2 * mi + 1] += v2 + v3;  sq[2 * mi + 1] += v2 * v2 + v3 * v3;
        }
#pragma unroll
    for (int off = 1; off <= 2; off <<= 1)
#pragma unroll
        for (int sl = 0; sl < 4; sl++) {
            sum[sl] += __shfl_xor_sync(0xffffffffu, sum[sl], off);
            sq[sl]  += __shfl_xor_sync(0xffffffffu, sq[sl],  off);
        }
    if (q == 0) {
#pragma unroll
        for (int sl = 0; sl < 4; sl++) {
            int lr = 32 * wr + 16 * (sl >> 1) + g + 8 * (sl & 1);
            sRed[wc][0][lr] = sum[sl];
            sRed[wc][1][lr] = sq[sl];
        }
    }
    __syncthreads();
    if (t < 64) {
        float S = 0.f, Q = 0.f;
#pragma unroll
        for (int k = 0; k < 8; k++) { S += sRed[k][0][t]; Q += sRed[k][1][t]; }
        float mu = S * (1.0f / OUTC);
        sMu[t]  = mu;
        sInv[t] = rsqrtf(Q * (1.0f / OUTC) - mu * mu + EPSF);
    }
    __syncthreads();

#pragma unroll
    for (int mi = 0; mi < 2; mi++) {
        int lr0 = 32 * wr + 16 * mi + g;
        int lr1 = lr0 + 8;
        float mu0 = sMu[lr0], in0 = sInv[lr0];
        float mu1 = sMu[lr1], in1 = sInv[lr1];
        float* o0 = out + (size_t)(ctaRow + lr0) * OUTC;
        float* o1 = out + (size_t)(ctaRow + lr1) * OUTC;
#pragma unroll
        for (int ni = 0; ni < 5; ni++) {
            int c0 = 40 * wc + 8 * ni + 2 * q;
            if (c0 < OUTC) {
                float ga = sGamma[c0], gb = sGamma[c0 + 1];
                float ba = sBeta[c0],  bb = sBeta[c0 + 1];
                float2 r0, r1;
                r0.x = (acc[mi][ni][0] - mu0) * in0 * ga + ba;
                r0.y = (acc[mi][ni][1] - mu0) * in0 * gb + bb;
                r1.x = (acc[mi][ni][2] - mu1) * in1 * ga + ba;
                r1.y = (acc[mi][ni][3] - mu1) * in1 * gb + bb;
                *(float2*)(o0 + c0) = r0;
                *(float2*)(o1 + c0) = r1;
            }
        }
    }
}

// ---------------------------------------------------------------------------
extern "C" void kernel_launch(void* const* d_in, const int* in_sizes, int n_in,
                              void* d_out, int out_size)
{
    const float* t1    = (const float*)d_in[0];
    const int*   ws    = (const int*)  d_in[1];
    const float* W     = (const float*)d_in[3];
    const float* blin  = (const float*)d_in[4];
    const float* gamma = (const float*)d_in[5];
    const float* beta  = (const float*)d_in[6];

    float* out = (float*)d_out;
    float* use = out + (size_t)NN * SS * OUTC;

    static bool attr_set = false;
    if (!attr_set) {
        cudaFuncSetAttribute(gemm_ln_kernel,
                             cudaFuncAttributeMaxDynamicSharedMemorySize, DYN_SMEM);
        attr_set = true;
    }

    prep_kernel<<<MR + 320, 128>>>(t1, ws, W, use);
    gemm_ln_kernel<<<SS, 512, DYN_SMEM>>>(blin, gamma, beta, out);
}